// round 8
// baseline (speedup 1.0000x reference)
#include <cuda_runtime.h>
#include <cuda_fp16.h>
#include <cuda_bf16.h>
#include <stdint.h>

#define L_SEQ   1024
#define BATCH   4
#define DMODEL  1024
#define PROJDIM 256
#define NHEAD   8
#define HDIM    32
#define DEPTH   4
#define VOCAB   32000
#define MROWS   (L_SEQ*BATCH)          // 4096
#define NBLK    (VOCAB/128)            // 250
#define QSCALE  0.17677669529663687f   // 1/sqrt(32)

// ------------------------- static device scratch -------------------------
__device__ __half  g_W1T  [DEPTH*PROJDIM*DMODEL];
__device__ __half  g_W2T  [DEPTH*2*PROJDIM*PROJDIM];
__device__ __half  g_W3T  [DEPTH*3*DMODEL*PROJDIM];
__device__ __half  g_WoutT[(size_t)VOCAB*DMODEL];
__device__ float   g_h32  [MROWS*DMODEL];
__device__ __half  g_h16  [MROWS*DMODEL];
__device__ __half  g_z    [MROWS*PROJDIM];
__device__ __half  g_kv   [MROWS*2*PROJDIM];
__device__ __half  g_ao   [MROWS*PROJDIM];
__device__ float   g_U    [3ull*MROWS*DMODEL];
__device__ float2  g_part [(size_t)MROWS*NBLK];
__device__ float   g_ly   [MROWS];

// ------------------------- device helpers -------------------------
__device__ __forceinline__ uint32_t packh2(float a, float b){
    __half2 h = __floats2half2_rn(a, b);
    return *reinterpret_cast<uint32_t*>(&h);
}
__device__ __forceinline__ void mma16816(float* c, const uint32_t* a, uint32_t b0, uint32_t b1){
    asm volatile(
        "mma.sync.aligned.m16n8k16.row.col.f32.f16.f16.f32 "
        "{%0,%1,%2,%3},{%4,%5,%6,%7},{%8,%9},{%0,%1,%2,%3};\n"
        : "+f"(c[0]), "+f"(c[1]), "+f"(c[2]), "+f"(c[3])
        : "r"(a[0]), "r"(a[1]), "r"(a[2]), "r"(a[3]), "r"(b0), "r"(b1));
}
__device__ __forceinline__ void ldsm4(uint32_t* r, uint32_t addr){
    asm volatile("ldmatrix.sync.aligned.m8n8.x4.shared.b16 {%0,%1,%2,%3}, [%4];\n"
        : "=r"(r[0]), "=r"(r[1]), "=r"(r[2]), "=r"(r[3]) : "r"(addr));
}
__device__ __forceinline__ void ldsm4t(uint32_t* r, uint32_t addr){
    asm volatile("ldmatrix.sync.aligned.m8n8.x4.trans.shared.b16 {%0,%1,%2,%3}, [%4];\n"
        : "=r"(r[0]), "=r"(r[1]), "=r"(r[2]), "=r"(r[3]) : "r"(addr));
}
__device__ __forceinline__ void cpasync16(void* smem, const void* gmem){
    uint32_t s = (uint32_t)__cvta_generic_to_shared(smem);
    asm volatile("cp.async.cg.shared.global [%0], [%1], 16;\n" :: "r"(s), "l"(gmem));
}
__device__ __forceinline__ void cpcommit(){ asm volatile("cp.async.commit_group;\n"); }
template<int N> __device__ __forceinline__ void cpwait(){ asm volatile("cp.async.wait_group %0;\n" :: "n"(N)); }

// ------------------------- weight transpose f32[R][C] -> half[C][R] -------------------------
__global__ void transpose_k(const float* __restrict__ in, __half* __restrict__ out, int R, int C){
    __shared__ float tile[32][33];
    const float* ip = in  + (size_t)blockIdx.z * R * C;
    __half*      op = out + (size_t)blockIdx.z * R * C;
    int c0 = blockIdx.x * 32, r0 = blockIdx.y * 32;
    int tx = threadIdx.x, ty = threadIdx.y;
    #pragma unroll
    for (int i = 0; i < 4; i++)
        tile[ty + 8*i][tx] = ip[(size_t)(r0 + ty + 8*i) * C + c0 + tx];
    __syncthreads();
    #pragma unroll
    for (int i = 0; i < 4; i++)
        op[(size_t)(c0 + ty + 8*i) * R + r0 + tx] = __float2half_rn(tile[tx][ty + 8*i]);
}

// ------------------------- embedding -------------------------
__global__ void embed_k(const int* __restrict__ x, const float* __restrict__ emb,
                        float* __restrict__ h32, __half* __restrict__ h16){
    int row = blockIdx.x;
    int xv = x[row];
    const float4* src = (const float4*)(emb + (size_t)xv * DMODEL);
    int i = threadIdx.x;                   // 256 threads, DMODEL/4 = 256
    float4 v = src[i];
    *(float4*)&h32[(size_t)row*DMODEL + i*4] = v;
    __half2 a = __floats2half2_rn(v.x, v.y), b = __floats2half2_rn(v.z, v.w);
    *(__half2*)&h16[(size_t)row*DMODEL + i*4]     = a;
    *(__half2*)&h16[(size_t)row*DMODEL + i*4 + 2] = b;
}

// ------------------------- generic fp16 GEMM: C[M=4096,N] = A[M,K] * B^T (B stored [N][K]) ----
// EPI 0: store half C.   EPI 1: scatter fp32 to U planes [3][M][1024].
// EPI 2: fused softmax partials (+bout) -> part[row][nblk]
template<int EPI>
__global__ void __launch_bounds__(256) gemm_k(
    const __half* __restrict__ A, const __half* __restrict__ B, int N, int K,
    __half* __restrict__ Ch, float* __restrict__ Cu,
    const float* __restrict__ bout, float2* __restrict__ part)
{
    __shared__ __half sA[2][128*40];
    __shared__ __half sB[2][128*40];
    __shared__ float2 sred[2][128];

    int tid = threadIdx.x;
    int warp = tid >> 5, lane = tid & 31;
    int wm = warp >> 1, wn = warp & 1;
    int bm = blockIdx.y * 128, bn = blockIdx.x * 128;

    float acc[2][8][4];
    #pragma unroll
    for (int i = 0; i < 2; i++)
        #pragma unroll
        for (int j = 0; j < 8; j++)
            #pragma unroll
            for (int q = 0; q < 4; q++) acc[i][j][q] = 0.f;

    const __half* Ag = A + (size_t)bm * K;
    const __half* Bg = B + (size_t)bn * K;
    int lrow = tid >> 2;           // 0..63
    int lcol = (tid & 3) * 8;      // 0,8,16,24

    auto issue = [&](int buf, int kt){
        int k0 = kt * 32;
        #pragma unroll
        for (int i = 0; i < 2; i++){
            int r = lrow + i * 64;
            cpasync16(&sA[buf][r*40 + lcol], Ag + (size_t)r*K + k0 + lcol);
            cpasync16(&sB[buf][r*40 + lcol], Bg + (size_t)r*K + k0 + lcol);
        }
    };

    int KT = K / 32;
    issue(0, 0); cpcommit();
    for (int kt = 0; kt < KT; kt++){
        int buf = kt & 1;
        if (kt + 1 < KT){ issue(buf ^ 1, kt + 1); cpcommit(); cpwait<1>(); }
        else            { cpwait<0>(); }
        __syncthreads();
        #pragma unroll
        for (int ks = 0; ks < 2; ks++){
            uint32_t aa[2][4];
            #pragma unroll
            for (int mi = 0; mi < 2; mi++){
                int r = wm*32 + mi*16 + (lane & 15);
                int c = ks*16 + (lane >> 4) * 8;
                ldsm4(aa[mi], (uint32_t)__cvta_generic_to_shared(&sA[buf][r*40 + c]));
            }
            uint32_t bb[4][4];
            #pragma unroll
            for (int nt = 0; nt < 4; nt++){
                int r = wn*64 + nt*16 + (lane & 15);
                int c = ks*16 + (lane >> 4) * 8;
                ldsm4(bb[nt], (uint32_t)__cvta_generic_to_shared(&sB[buf][r*40 + c]));
            }
            #pragma unroll
            for (int mi = 0; mi < 2; mi++)
                #pragma unroll
                for (int nj = 0; nj < 8; nj++)
                    mma16816(acc[mi][nj], aa[mi], bb[nj>>1][nj&1], bb[nj>>1][(nj&1)+2]);
        }
        __syncthreads();
    }

    if (EPI == 0){
        #pragma unroll
        for (int mi = 0; mi < 2; mi++)
            #pragma unroll
            for (int nj = 0; nj < 8; nj++){
                int r = bm + wm*32 + mi*16 + (lane >> 2);
                int c = bn + wn*64 + nj*8 + (lane & 3)*2;
                *(__half2*)&Ch[(size_t)r*N + c]     = __floats2half2_rn(acc[mi][nj][0], acc[mi][nj][1]);
                *(__half2*)&Ch[(size_t)(r+8)*N + c] = __floats2half2_rn(acc[mi][nj][2], acc[mi][nj][3]);
            }
    } else if (EPI == 1){
        #pragma unroll
        for (int mi = 0; mi < 2; mi++)
            #pragma unroll
            for (int nj = 0; nj < 8; nj++){
                int r = bm + wm*32 + mi*16 + (lane >> 2);
                int cbase = bn + wn*64 + nj*8 + (lane & 3)*2;
                #pragma unroll
                for (int q = 0; q < 4; q++){
                    int n = cbase + (q & 1);
                    int row = r + (q >> 1) * 8;
                    Cu[(size_t)(n % 3) * MROWS * DMODEL + (size_t)row * DMODEL + (n / 3)] = acc[mi][nj][q];
                }
            }
    } else {
        float bo[8][2];
        #pragma unroll
        for (int nj = 0; nj < 8; nj++){
            int cg = bn + wn*64 + nj*8 + (lane & 3)*2;
            bo[nj][0] = bout[cg]; bo[nj][1] = bout[cg+1];
        }
        float2 mr[2][2];
        #pragma unroll
        for (int mi = 0; mi < 2; mi++)
            #pragma unroll
            for (int hh = 0; hh < 2; hh++){
                float mx = -1e30f;
                #pragma unroll
                for (int nj = 0; nj < 8; nj++){
                    float v0 = acc[mi][nj][hh*2]   + bo[nj][0];
                    float v1 = acc[mi][nj][hh*2+1] + bo[nj][1];
                    acc[mi][nj][hh*2] = v0; acc[mi][nj][hh*2+1] = v1;
                    mx = fmaxf(mx, fmaxf(v0, v1));
                }
                mx = fmaxf(mx, __shfl_xor_sync(0xffffffffu, mx, 1));
                mx = fmaxf(mx, __shfl_xor_sync(0xffffffffu, mx, 2));
                float sm = 0.f;
                #pragma unroll
                for (int nj = 0; nj < 8; nj++)
                    sm += __expf(acc[mi][nj][hh*2] - mx) + __expf(acc[mi][nj][hh*2+1] - mx);
                sm += __shfl_xor_sync(0xffffffffu, sm, 1);
                sm += __shfl_xor_sync(0xffffffffu, sm, 2);
                mr[mi][hh] = make_float2(mx, sm);
            }
        __syncthreads();
        if ((lane & 3) == 0){
            #pragma unroll
            for (int mi = 0; mi < 2; mi++)
                #pragma unroll
                for (int hh = 0; hh < 2; hh++){
                    int r = wm*32 + mi*16 + (lane >> 2) + hh*8;
                    sred[wn][r] = mr[mi][hh];
                }
        }
        __syncthreads();
        if (tid < 128){
            float2 p0 = sred[0][tid], p1 = sred[1][tid];
            float Mx = fmaxf(p0.x, p1.x);
            float S  = p0.y * __expf(p0.x - Mx) + p1.y * __expf(p1.x - Mx);
            part[(size_t)(bm + tid) * gridDim.x + blockIdx.x] = make_float2(Mx, S);
        }
    }
}

// ------------------------- fused flash attention + rezero residual -------------------------
// grid (8 q-blocks, NHEAD, BATCH); 256 threads = 8 warps, warp w owns q rows [16w,16w+16)
__global__ void __launch_bounds__(256) attn_k(
    const __half* __restrict__ z, const __half* __restrict__ kv,
    __half* __restrict__ ao, const float* __restrict__ alpha_p, int layer)
{
    __shared__ __half sQ[128*40];
    __shared__ __half sK[128*40];
    __shared__ __half sV[128*40];

    int qb = blockIdx.x, head = blockIdx.y, b = blockIdx.z;
    int tid = threadIdx.x, warp = tid >> 5, lane = tid & 31;
    float alpha = alpha_p[layer];

    // load Q tile (128 x 32 halves)
    #pragma unroll
    for (int i = 0; i < 2; i++){
        int c = tid + i*256; int r = c >> 2; int cc = (c & 3) * 8;
        size_t g = (size_t)((qb*128 + r) * BATCH + b) * PROJDIM + head*32 + cc;
        cpasync16(&sQ[r*40 + cc], z + g);
    }
    cpcommit(); cpwait<0>(); __syncthreads();

    uint32_t aq[2][4];
    #pragma unroll
    for (int ks = 0; ks < 2; ks++){
        int r = warp*16 + (lane & 15);
        int c = ks*16 + (lane >> 4) * 8;
        ldsm4(aq[ks], (uint32_t)__cvta_generic_to_shared(&sQ[r*40 + c]));
    }

    float m0 = -1e30f, m1 = -1e30f, l0 = 0.f, l1 = 0.f;
    float o[4][4];
    #pragma unroll
    for (int i = 0; i < 4; i++){ o[i][0]=o[i][1]=o[i][2]=o[i][3]=0.f; }
    int qrow0 = qb*128 + warp*16 + (lane >> 2);

    for (int jb = 0; jb <= qb; jb++){
        #pragma unroll
        for (int i = 0; i < 2; i++){
            int c = tid + i*256; int r = c >> 2; int cc = (c & 3) * 8;
            size_t g = (size_t)((jb*128 + r) * BATCH + b) * (2*PROJDIM) + head*32 + cc;
            cpasync16(&sK[r*40 + cc], kv + g);
            cpasync16(&sV[r*40 + cc], kv + g + PROJDIM);
        }
        cpcommit(); cpwait<0>(); __syncthreads();

        float s[16][4];
        #pragma unroll
        for (int i = 0; i < 16; i++){ s[i][0]=s[i][1]=s[i][2]=s[i][3]=0.f; }
        #pragma unroll
        for (int ks = 0; ks < 2; ks++){
            #pragma unroll
            for (int nt = 0; nt < 8; nt++){
                uint32_t bb[4];
                int r = nt*16 + (lane & 15);
                int c = ks*16 + (lane >> 4) * 8;
                ldsm4(bb, (uint32_t)__cvta_generic_to_shared(&sK[r*40 + c]));
                mma16816(s[2*nt],   aq[ks], bb[0], bb[2]);
                mma16816(s[2*nt+1], aq[ks], bb[1], bb[3]);
            }
        }
        // scale + causal mask + row max
        float mx0 = -1e30f, mx1 = -1e30f;
        #pragma unroll
        for (int nj = 0; nj < 16; nj++){
            int col = jb*128 + nj*8 + (lane & 3)*2;
            #pragma unroll
            for (int q = 0; q < 2; q++){
                s[nj][q]   = s[nj][q]  *QSCALE + ((col + q > qrow0)     ? -10000.f : 0.f);
                s[nj][q+2] = s[nj][q+2]*QSCALE + ((col + q > qrow0 + 8) ? -10000.f : 0.f);
            }
            mx0 = fmaxf(mx0, fmaxf(s[nj][0], s[nj][1]));
            mx1 = fmaxf(mx1, fmaxf(s[nj][2], s[nj][3]));
        }
        mx0 = fmaxf(mx0, __shfl_xor_sync(0xffffffffu, mx0, 1));
        mx0 = fmaxf(mx0, __shfl_xor_sync(0xffffffffu, mx0, 2));
        mx1 = fmaxf(mx1, __shfl_xor_sync(0xffffffffu, mx1, 1));
        mx1 = fmaxf(mx1, __shfl_xor_sync(0xffffffffu, mx1, 2));
        float nm0 = fmaxf(m0, mx0), nm1 = fmaxf(m1, mx1);
        float sc0 = __expf(m0 - nm0), sc1 = __expf(m1 - nm1);
        l0 *= sc0; l1 *= sc1;
        #pragma unroll
        for (int nt = 0; nt < 4; nt++){
            o[nt][0] *= sc0; o[nt][1] *= sc0; o[nt][2] *= sc1; o[nt][3] *= sc1;
        }
        m0 = nm0; m1 = nm1;

        uint32_t ph[16][2];
        float rs0 = 0.f, rs1 = 0.f;
        #pragma unroll
        for (int nj = 0; nj < 16; nj++){
            float p0 = __expf(s[nj][0] - nm0), p1 = __expf(s[nj][1] - nm0);
            float p2 = __expf(s[nj][2] - nm1), p3 = __expf(s[nj][3] - nm1);
            rs0 += p0 + p1; rs1 += p2 + p3;
            ph[nj][0] = packh2(p0, p1);
            ph[nj][1] = packh2(p2, p3);
        }
        rs0 += __shfl_xor_sync(0xffffffffu, rs0, 1);
        rs0 += __shfl_xor_sync(0xffffffffu, rs0, 2);
        rs1 += __shfl_xor_sync(0xffffffffu, rs1, 1);
        rs1 += __shfl_xor_sync(0xffffffffu, rs1, 2);
        l0 += rs0; l1 += rs1;

        // P(128x128) * V(128x32)
        #pragma unroll
        for (int ks = 0; ks < 8; ks++){
            uint32_t a[4] = { ph[2*ks][0], ph[2*ks][1], ph[2*ks+1][0], ph[2*ks+1][1] };
            #pragma unroll
            for (int nt4 = 0; nt4 < 2; nt4++){
                uint32_t bv[4];
                int r = ks*16 + (lane & 7) + ((lane >> 3) & 1) * 8;
                int c = nt4*16 + (lane >> 4) * 8;
                ldsm4t(bv, (uint32_t)__cvta_generic_to_shared(&sV[r*40 + c]));
                mma16816(o[nt4*2],   a, bv[0], bv[1]);
                mma16816(o[nt4*2+1], a, bv[2], bv[3]);
            }
        }
        __syncthreads();
    }

    float il0 = __fdividef(1.f, l0), il1 = __fdividef(1.f, l1);
    #pragma unroll
    for (int nt = 0; nt < 4; nt++){
        int r  = qb*128 + warp*16 + (lane >> 2);
        int cc = head*32 + nt*8 + (lane & 3)*2;
        size_t i0 = (size_t)(r * BATCH + b) * PROJDIM + cc;
        size_t i1 = (size_t)((r + 8) * BATCH + b) * PROJDIM + cc;
        float2 z0 = __half22float2(*(const __half2*)&z[i0]);
        float2 z1 = __half22float2(*(const __half2*)&z[i1]);
        *(__half2*)&ao[i0] = __floats2half2_rn(alpha*o[nt][0]*il0 + z0.x, alpha*o[nt][1]*il0 + z0.y);
        *(__half2*)&ao[i1] = __floats2half2_rn(alpha*o[nt][2]*il1 + z1.x, alpha*o[nt][3]*il1 + z1.y);
    }
}

// ------------------------- SRU elementwise recurrence (in-place on h) -------------------------
__global__ void sru_k(const float* __restrict__ U, float* __restrict__ h32,
                      __half* __restrict__ h16, const float* __restrict__ hidden,
                      const float* __restrict__ wc, const float* __restrict__ bias, int layer)
{
    int idx = blockIdx.x * 64 + threadIdx.x;      // 64 blocks x 64 threads = 4096 chains
    int b = idx >> 10, d = idx & 1023;
    float c = hidden[((size_t)layer * BATCH + b) * DMODEL + d];
    float vf = wc[layer*2*DMODEL + d],          vr = wc[layer*2*DMODEL + DMODEL + d];
    float bf = bias[layer*2*DMODEL + d],        br = bias[layer*2*DMODEL + DMODEL + d];
    const size_t MD = (size_t)MROWS * DMODEL;

    float bu0[4], bu1[4], bu2[4], brr[4];
    #pragma unroll
    for (int i = 0; i < 4; i++){
        size_t off = (size_t)(i * BATCH + b) * DMODEL + d;
        bu0[i] = U[off]; bu1[i] = U[MD + off]; bu2[i] = U[2*MD + off]; brr[i] = h32[off];
    }
    for (int t = 0; t < L_SEQ; t += 4){
        float nu0[4], nu1[4], nu2[4], nr[4];
        if (t + 4 < L_SEQ){
            #pragma unroll
            for (int i = 0; i < 4; i++){
                size_t off = (size_t)((t + 4 + i) * BATCH + b) * DMODEL + d;
                nu0[i] = U[off]; nu1[i] = U[MD + off]; nu2[i] = U[2*MD + off]; nr[i] = h32[off];
            }
        } else {
            #pragma unroll
            for (int i = 0; i < 4; i++){ nu0[i]=nu1[i]=nu2[i]=nr[i]=0.f; }
        }
        #pragma unroll
        for (int i = 0; i < 4; i++){
            float f = __fdividef(1.f, 1.f + __expf(-(bu1[i] + bf + vf * c)));
            c = f * c + (1.f - f) * bu0[i];
            float r = __fdividef(1.f, 1.f + __expf(-(bu2[i] + br + vr * c)));
            float h = r * c + (1.f - r) * brr[i];
            size_t off = (size_t)((t + i) * BATCH + b) * DMODEL + d;
            h32[off] = h;
            h16[off] = __float2half_rn(h);
        }
        #pragma unroll
        for (int i = 0; i < 4; i++){ bu0[i]=nu0[i]; bu1[i]=nu1[i]; bu2[i]=nu2[i]; brr[i]=nr[i]; }
    }
}

// ------------------------- target logit: warp-per-row dot(h, Wout[:,y]) -------------------------
__global__ void logity_k(const __half* __restrict__ h16, const __half* __restrict__ WT,
                         const int* __restrict__ y, const float* __restrict__ bout,
                         float* __restrict__ out)
{
    int w = (blockIdx.x * 256 + threadIdx.x) >> 5;
    int lane = threadIdx.x & 31;
    int yv = y[w];
    const __half2* hp = (const __half2*)(h16 + (size_t)w * DMODEL);
    const __half2* wp = (const __half2*)(WT + (size_t)yv * DMODEL);
    float sum = 0.f;
    #pragma unroll 4
    for (int i = lane; i < DMODEL/2; i += 32){
        float2 a = __half22float2(hp[i]);
        float2 q = __half22float2(wp[i]);
        sum += a.x*q.x + a.y*q.y;
    }
    #pragma unroll
    for (int o = 16; o; o >>= 1) sum += __shfl_xor_sync(0xffffffffu, sum, o);
    if (lane == 0) out[w] = sum + bout[yv];
}

// ------------------------- final logsumexp reduce + loss -------------------------
__global__ void loss_k(const float2* __restrict__ part, const float* __restrict__ ly,
                       float* __restrict__ loss)
{
    int w = (blockIdx.x * 256 + threadIdx.x) >> 5;
    int lane = threadIdx.x & 31;
    float M = -1e30f, S = 0.f;
    for (int i = lane; i < NBLK; i += 32){
        float2 p = part[(size_t)w * NBLK + i];
        float nM = fmaxf(M, p.x);
        S = S * __expf(M - nM) + p.y * __expf(p.x - nM);
        M = nM;
    }
    #pragma unroll
    for (int o = 16; o; o >>= 1){
        float oM = __shfl_xor_sync(0xffffffffu, M, o);
        float oS = __shfl_xor_sync(0xffffffffu, S, o);
        float nM = fmaxf(M, oM);
        S = S * __expf(M - nM) + oS * __expf(oM - nM);
        M = nM;
    }
    if (lane == 0) loss[w] = (M + __logf(S)) - ly[w];
}

// ------------------------- host orchestration -------------------------
extern "C" void kernel_launch(void* const* d_in, const int* in_sizes, int n_in,
                              void* d_out, int out_size)
{
    const int*   x      = (const int*)  d_in[0];
    const int*   y      = (const int*)  d_in[1];
    const float* hidden = (const float*)d_in[2];
    const float* embW   = (const float*)d_in[3];
    const float* W1     = (const float*)d_in[4];
    const float* W2     = (const float*)d_in[5];
    const float* W3     = (const float*)d_in[6];
    const float* alpha  = (const float*)d_in[7];
    const float* wc     = (const float*)d_in[8];
    const float* bias   = (const float*)d_in[9];
    const float* Wout   = (const float*)d_in[10];
    const float* bout   = (const float*)d_in[11];
    float* loss = (float*)d_out;
    (void)in_sizes; (void)n_in; (void)out_size;

    void *pW1T, *pW2T, *pW3T, *pWoutT, *ph32, *ph16, *pz, *pkv, *pao, *pU, *ppart, *ply;
    cudaGetSymbolAddress(&pW1T,   g_W1T);
    cudaGetSymbolAddress(&pW2T,   g_W2T);
    cudaGetSymbolAddress(&pW3T,   g_W3T);
    cudaGetSymbolAddress(&pWoutT, g_WoutT);
    cudaGetSymbolAddress(&ph32,   g_h32);
    cudaGetSymbolAddress(&ph16,   g_h16);
    cudaGetSymbolAddress(&pz,     g_z);
    cudaGetSymbolAddress(&pkv,    g_kv);
    cudaGetSymbolAddress(&pao,    g_ao);
    cudaGetSymbolAddress(&pU,     g_U);
    cudaGetSymbolAddress(&ppart,  g_part);
    cudaGetSymbolAddress(&ply,    g_ly);

    dim3 tb(32, 8);
    transpose_k<<<dim3(PROJDIM/32,   DMODEL/32,  DEPTH), tb>>>(W1,   (__half*)pW1T,   DMODEL,  PROJDIM);
    transpose_k<<<dim3(2*PROJDIM/32, PROJDIM/32, DEPTH), tb>>>(W2,   (__half*)pW2T,   PROJDIM, 2*PROJDIM);
    transpose_k<<<dim3(3*DMODEL/32,  PROJDIM/32, DEPTH), tb>>>(W3,   (__half*)pW3T,   PROJDIM, 3*DMODEL);
    transpose_k<<<dim3(VOCAB/32,     DMODEL/32,  1),     tb>>>(Wout, (__half*)pWoutT, DMODEL,  VOCAB);

    embed_k<<<MROWS, 256>>>(x, embW, (float*)ph32, (__half*)ph16);

    for (int lyr = 0; lyr < DEPTH; lyr++){
        gemm_k<0><<<dim3(PROJDIM/128, MROWS/128), 256>>>(
            (__half*)ph16, (__half*)pW1T + (size_t)lyr*PROJDIM*DMODEL,
            PROJDIM, DMODEL, (__half*)pz, nullptr, nullptr, nullptr);
        gemm_k<0><<<dim3(2*PROJDIM/128, MROWS/128), 256>>>(
            (__half*)pz, (__half*)pW2T + (size_t)lyr*2*PROJDIM*PROJDIM,
            2*PROJDIM, PROJDIM, (__half*)pkv, nullptr, nullptr, nullptr);
        attn_k<<<dim3(L_SEQ/128, NHEAD, BATCH), 256>>>(
            (__half*)pz, (__half*)pkv, (__half*)pao, alpha, lyr);
        gemm_k<1><<<dim3(3*DMODEL/128, MROWS/128), 256>>>(
            (__half*)pao, (__half*)pW3T + (size_t)lyr*3*DMODEL*PROJDIM,
            3*DMODEL, PROJDIM, nullptr, (float*)pU, nullptr, nullptr);
        sru_k<<<64, 64>>>((float*)pU, (float*)ph32, (__half*)ph16, hidden, wc, bias, lyr);
    }

    gemm_k<2><<<dim3(VOCAB/128, MROWS/128), 256>>>(
        (__half*)ph16, (__half*)pWoutT, VOCAB, DMODEL,
        nullptr, nullptr, bout, (float2*)ppart);
    logity_k<<<MROWS/8, 256>>>((__half*)ph16, (__half*)pWoutT, y, bout, (float*)ply);
    loss_k<<<MROWS/8, 256>>>((const float2*)ppart, (const float*)ply, loss);
}